// round 4
// baseline (speedup 1.0000x reference)
#include <cuda_runtime.h>
#include <cuda_bf16.h>

#define IMG_S   4096
#define N_DOTS  100
#define TILE    32
#define NTHREADS 256

// Block = 32x32 tile. Thread t: x = tx0 + (t&7)*4, y = ty0 + (t>>3); one
// float4 quad per thread, per channel.
__global__ __launch_bounds__(NTHREADS, 8)
void PatchTrainer_dots_kernel(const float* __restrict__ patch,
                              const float* __restrict__ centers,
                              const float* __restrict__ radii,
                              const float* __restrict__ colors,
                              float* __restrict__ out) {
    __shared__ float4   sdot[N_DOTS];   // (xc, yc, r2, idx) descending, truncated
    __shared__ float4   scol4[N_DOTS];  // (r, g, b, 0)
    __shared__ unsigned s_inter[4];
    __shared__ unsigned s_cont[4];

    const int tid = threadIdx.x;
    const int tx0 = blockIdx.x * TILE;
    const int ty0 = blockIdx.y * TILE;

    // ---- transform + cull: thread d < 100 owns dot d ----
    float xc = 0.f, yc = 0.f, r2 = 0.f;
    bool inter = false, cont = false;
    if (tid < N_DOTS) {
        xc = floorf(__fmul_rn(centers[2 * tid + 0], 4096.0f));
        yc = floorf(__fmul_rn(centers[2 * tid + 1], 4096.0f));
        float r = floorf(__fmul_rn(radii[tid], 819.2f));
        r2 = __fmul_rn(r, r);
        scol4[tid] = make_float4(colors[3 * tid], colors[3 * tid + 1],
                                 colors[3 * tid + 2], 0.f);

        // Intersect: nearest tile pixel, reference rounding chain (monotone
        // rounding => never misses a covered pixel).
        float nx = fminf(fmaxf(xc, (float)tx0), (float)(tx0 + TILE - 1));
        float ny = fminf(fmaxf(yc, (float)ty0), (float)(ty0 + TILE - 1));
        float ndx = __fadd_rn(nx, -xc), ndy = __fadd_rn(ny, -yc);
        inter = __fadd_rn(__fmul_rn(ndx, ndx), __fmul_rn(ndy, ndy)) <= r2;

        // Contains: farthest corner |dx|,|dy|, same rounding chain.
        float ax = fmaxf(fabsf(__fadd_rn((float)tx0, -xc)),
                         fabsf(__fadd_rn((float)(tx0 + TILE - 1), -xc)));
        float ay = fmaxf(fabsf(__fadd_rn((float)ty0, -yc)),
                         fabsf(__fadd_rn((float)(ty0 + TILE - 1), -yc)));
        cont = __fadd_rn(__fmul_rn(ax, ax), __fmul_rn(ay, ay)) <= r2;
    }
    unsigned bi = __ballot_sync(0xffffffffu, inter);
    unsigned bc = __ballot_sync(0xffffffffu, cont);
    if ((tid & 31) == 0 && tid < 128) {
        s_inter[tid >> 5] = bi;
        s_cont[tid >> 5]  = bc;
    }
    __syncthreads();

    // ---- base (highest containing dot) + eligible masks, all threads ----
    const unsigned cw0 = s_cont[0], cw1 = s_cont[1], cw2 = s_cont[2], cw3 = s_cont[3];
    int base = -1;
    if      (cw3) base = 96 + 31 - __clz(cw3);
    else if (cw2) base = 64 + 31 - __clz(cw2);
    else if (cw1) base = 32 + 31 - __clz(cw1);
    else if (cw0) base =      31 - __clz(cw0);

    unsigned e0 = s_inter[0], e1 = s_inter[1], e2 = s_inter[2], e3 = s_inter[3];
    if (base >= 0) {
        const int bw = base >> 5;
        const unsigned keep = 0xffffffffu << (base & 31);
        if      (bw == 0) { e0 &= keep; }
        else if (bw == 1) { e0 = 0; e1 &= keep; }
        else if (bw == 2) { e0 = 0; e1 = 0; e2 &= keep; }
        else              { e0 = 0; e1 = 0; e2 = 0; e3 &= keep; }
    }
    const int cnt = __popc(e0) + __popc(e1) + __popc(e2) + __popc(e3);

    // ---- parallel compaction into descending list ----
    if (tid < N_DOTS && inter && (base < 0 || tid >= base)) {
        const int w = tid >> 5, b = tid & 31;
        const unsigned own = (w == 0) ? e0 : (w == 1) ? e1 : (w == 2) ? e2 : e3;
        int rank = __popc(own & (0xFFFFFFFEu << b));
        if (w < 1) rank += __popc(e1);
        if (w < 2) rank += __popc(e2);
        if (w < 3) rank += __popc(e3);
        sdot[rank] = make_float4(xc, yc, r2, __int_as_float(tid));
    }
    __syncthreads();

    const int x = tx0 + ((tid & 7) << 2);
    const int y = ty0 + (tid >> 3);
    const size_t pix   = (size_t)y * IMG_S + (size_t)x;
    const size_t plane = (size_t)IMG_S * IMG_S;

    // ---- fast path: solid tile ----
    if (base >= 0 && cnt == 1) {
        const float4 cc = scol4[base];
        __stcs(reinterpret_cast<float4*>(out + pix),
               make_float4(cc.x, cc.x, cc.x, cc.x));
        __stcs(reinterpret_cast<float4*>(out + plane + pix),
               make_float4(cc.y, cc.y, cc.y, cc.y));
        __stcs(reinterpret_cast<float4*>(out + 2 * plane + pix),
               make_float4(cc.z, cc.z, cc.z, cc.z));
        return;
    }

    // ---- fast path: untouched tile (pure copy) ----
    if (cnt == 0) {
        #pragma unroll
        for (int c = 0; c < 3; ++c) {
            float4 a = __ldcs(reinterpret_cast<const float4*>(patch + c * plane + pix));
            __stcs(reinterpret_cast<float4*>(out + c * plane + pix), a);
        }
        return;
    }

    // ---- per-pixel descending loop: first covering dot wins ----
    const float yf  = (float)y;
    const float x0f = (float)x;

    int b0 = -1, b1 = -1, b2 = -1, b3 = -1;

    for (int k = 0; k < cnt; ++k) {
        const float4 dv = sdot[k];
        const int    d  = __float_as_int(dv.w);

        const float dy  = __fadd_rn(yf, -dv.y);
        const float dy2 = __fmul_rn(dy, dy);
        const float dx0 = __fadd_rn(x0f, -dv.x);
        const float dx1 = dx0 + 1.0f;   // exact integer offsets in f32
        const float dx2 = dx0 + 2.0f;
        const float dx3 = dx0 + 3.0f;

        if (b0 < 0 && __fadd_rn(__fmul_rn(dx0, dx0), dy2) <= dv.z) b0 = d;
        if (b1 < 0 && __fadd_rn(__fmul_rn(dx1, dx1), dy2) <= dv.z) b1 = d;
        if (b2 < 0 && __fadd_rn(__fmul_rn(dx2, dx2), dy2) <= dv.z) b2 = d;
        if (b3 < 0 && __fadd_rn(__fmul_rn(dx3, dx3), dy2) <= dv.z) b3 = d;

        if (__all_sync(0xffffffffu, min(min(b0, b1), min(b2, b3)) >= 0)) break;
    }

    const float4 c0 = scol4[max(b0, 0)];
    const float4 c1 = scol4[max(b1, 0)];
    const float4 c2 = scol4[max(b2, 0)];
    const float4 c3 = scol4[max(b3, 0)];
    const bool need_in = (b0 < 0) | (b1 < 0) | (b2 < 0) | (b3 < 0);

    #pragma unroll
    for (int c = 0; c < 3; ++c) {
        float4 v = make_float4(0.f, 0.f, 0.f, 0.f);
        if (need_in)
            v = __ldcs(reinterpret_cast<const float4*>(patch + c * plane + pix));
        float4 o;
        o.x = (b0 >= 0) ? ((c == 0) ? c0.x : (c == 1) ? c0.y : c0.z) : v.x;
        o.y = (b1 >= 0) ? ((c == 0) ? c1.x : (c == 1) ? c1.y : c1.z) : v.y;
        o.z = (b2 >= 0) ? ((c == 0) ? c2.x : (c == 1) ? c2.y : c2.z) : v.z;
        o.w = (b3 >= 0) ? ((c == 0) ? c3.x : (c == 1) ? c3.y : c3.z) : v.w;
        __stcs(reinterpret_cast<float4*>(out + c * plane + pix), o);
    }
}

extern "C" void kernel_launch(void* const* d_in, const int* in_sizes, int n_in,
                              void* d_out, int out_size) {
    const float* adv_patch = (const float*)d_in[0];
    const float* centers   = (const float*)d_in[1];
    const float* radii     = (const float*)d_in[2];
    const float* colors    = (const float*)d_in[3];
    float* out = (float*)d_out;

    dim3 grid(IMG_S / TILE, IMG_S / TILE);  // 128 x 128 tiles
    PatchTrainer_dots_kernel<<<grid, NTHREADS>>>(adv_patch, centers, radii,
                                                 colors, out);
}